// round 14
// baseline (speedup 1.0000x reference)
#include <cuda_runtime.h>
#include <math.h>

#define HH 128
#define WW 128
#define SAT_STRIDE 132           // row stride in floats (mult of 4; data cols 4..131)
#define MAX_PATCH 8192
#define MAX_C 2048
#define GRP 64                   // channels per transpose group

// Scratch (no allocations allowed).
__device__ float g_outT[(size_t)MAX_C * MAX_PATCH];   // [C][N] transposed
__device__ unsigned g_grp[MAX_C / GRP];  // monotone group counters (replay-safe)

// ---------------------------------------------------------------------------
// Inline patch-coordinate math, bit-exact vs. the reference:
//   n = i * nrois + r ;  round == rintf (round-half-even == jnp.round)
// ---------------------------------------------------------------------------
__device__ __forceinline__ void patch_coords(
    const float4* __restrict__ roi4, int n, int nrois, int p,
    int4& q, float& inv) {
    int i = n / nrois;     // patch index within roi
    int r = n - i * nrois; // roi index

    float4 rb = roi4[r];
    float xmin = rb.x, ymin = rb.y, xmax = rb.z, ymax = rb.w;

    float ix = (float)(i % p);
    float iy = (float)(i / p);
    float pf = (float)p;

    float wstep = __fdiv_rn(__fadd_rn(xmax, -xmin), pf);
    float hstep = __fdiv_rn(__fadd_rn(ymax, -ymin), pf);

    float ax = __fadd_rn(xmin, __fmul_rn(ix, wstep));
    float ay = __fadd_rn(ymin, __fmul_rn(iy, hstep));

    int x0 = (int)rintf(ax);
    int y0 = (int)rintf(ay);
    int x1 = (int)rintf(__fadd_rn(ax, wstep));
    int y1 = (int)rintf(__fadd_rn(ay, hstep));

    // Reference divides by the RAW (unclamped) count.
    float cnt = (float)((y1 - y0) * (x1 - x0));
    inv = 1.0f / fmaxf(cnt, 1.0f);

    // Clamp only for safe SAT indexing.
    x0 = min(max(x0, 0), WW);  x1 = min(max(x1, 0), WW);
    y0 = min(max(y0, 0), HH);  y1 = min(max(y1, 0), HH);
    q = make_int4(x0, y0, x1, y1);
}

// ---------------------------------------------------------------------------
// One CTA (256 thr, 3 CTAs/SM) per channel; grid = C (perfect balance).
//   Phase A: SAT build + gather, coalesced write to g_outT[c][*].
//   Epilogue: threadfence + atomicAdd on the 64-channel group counter
//   (monotone -> graph-replay-safe, never waits -> deadlock-free). The
//   64th arriver transposes its group's 64xN strip to out via smem tiles.
//   Replaces the second kernel (~5.5us launch floor) AND avoids the global
//   barrier's straggler tax (R13 regression).
// Fast path requires N%64==0 && C%64==0; otherwise gather stores directly
// to out (uncoalesced but correct).
// ---------------------------------------------------------------------------
__global__ void __launch_bounds__(256, 3) sat_pool_tr_kernel(
    const float* __restrict__ fm, const float* __restrict__ roi,
    float* __restrict__ out, int C, int N, int nrois, int p, int fast) {
    extern __shared__ float sat[];   // HH * SAT_STRIDE floats = 67584 B
    __shared__ unsigned s_last;

    const int c    = blockIdx.x;
    const int tid  = threadIdx.x;
    const int warp = tid >> 5;
    const int lane = tid & 31;
    const float4* roi4 = reinterpret_cast<const float4*>(roi);

    // --- Phase A1: fused high-MLP load + row prefix scan ---
    const float4* src =
        reinterpret_cast<const float4*>(fm + (size_t)c * HH * WW);
    #pragma unroll
    for (int half = 0; half < 2; half++) {
        const int rbase = warp * 16 + half * 8;
        float4 v[8];
        #pragma unroll
        for (int k = 0; k < 8; k++)               // 8 LDGs in flight
            v[k] = src[(rbase + k) * (WW / 4) + lane];
        #pragma unroll
        for (int k = 0; k < 8; k++) {             // independent scan chains
            float4 t = v[k];
            t.y += t.x; t.z += t.y; t.w += t.z;   // intra-quad scan
            float s = t.w;
            #pragma unroll
            for (int d = 1; d < 32; d <<= 1) {    // warp scan of quad sums
                float u = __shfl_up_sync(0xffffffffu, s, d);
                if (lane >= d) s += u;
            }
            float excl = s - t.w;
            t.x += excl; t.y += excl; t.z += excl; t.w += excl;
            *reinterpret_cast<float4*>(
                &sat[(rbase + k) * SAT_STRIDE + 4 + lane * 4]) = t;
        }
    }
    if (tid < HH) sat[tid * SAT_STRIDE + 3] = 0.0f;   // x = -1 boundary col
    __syncthreads();

    // --- Phase A2: column scan, 2-way split ---
    {
        int col  = tid & 127;
        int half = tid >> 7;
        float* ptr = &sat[(half * 64) * SAT_STRIDE + 4 + col];
        float acc = 0.0f;
        #pragma unroll 8
        for (int y = 0; y < 64; y++) {
            acc += ptr[y * SAT_STRIDE];
            ptr[y * SAT_STRIDE] = acc;
        }
    }
    __syncthreads();

    // --- Phase A3: gather ---
    const float* r63 = &sat[63 * SAT_STRIDE + 3];
    if (fast) {
        float* orow = &g_outT[(size_t)c * N];
        for (int n4 = tid * 4; n4 < N; n4 += 1024) {
            float res[4];
            #pragma unroll
            for (int k = 0; k < 4; k++) {
                int4 q; float inv;
                patch_coords(roi4, n4 + k, nrois, p, q, inv);
                int yb = max(q.w, 1) - 1;
                int ya = max(q.y, 1) - 1;
                float mbot  = (q.y > 0) ? 1.0f : 0.0f;
                float vmask = (q.z > q.x && q.w > q.y) ? 1.0f : 0.0f;
                float d63 = r63[q.z] - r63[q.x];
                const float* rb = &sat[yb * SAT_STRIDE + 3];
                const float* ra = &sat[ya * SAT_STRIDE + 3];
                float sb = (rb[q.z] - rb[q.x]) + ((yb >= 64) ? d63 : 0.0f);
                float sa = (ra[q.z] - ra[q.x]) + ((ya >= 64) ? d63 : 0.0f);
                res[k] = (sb - mbot * sa) * vmask * inv;
            }
            *reinterpret_cast<float4*>(&orow[n4]) =
                make_float4(res[0], res[1], res[2], res[3]);
        }
    } else {
        // Generic path: store directly (uncoalesced), no transpose stage.
        for (int n = tid; n < N; n += 256) {
            int4 q; float inv;
            patch_coords(roi4, n, nrois, p, q, inv);
            int yb = max(q.w, 1) - 1;
            int ya = max(q.y, 1) - 1;
            float mbot  = (q.y > 0) ? 1.0f : 0.0f;
            float vmask = (q.z > q.x && q.w > q.y) ? 1.0f : 0.0f;
            float d63 = r63[q.z] - r63[q.x];
            const float* rb = &sat[yb * SAT_STRIDE + 3];
            const float* ra = &sat[ya * SAT_STRIDE + 3];
            float sb = (rb[q.z] - rb[q.x]) + ((yb >= 64) ? d63 : 0.0f);
            float sa = (ra[q.z] - ra[q.x]) + ((ya >= 64) ? d63 : 0.0f);
            out[(size_t)n * C + c] = (sb - mbot * sa) * vmask * inv;
        }
        return;
    }
    __syncthreads();   // all g_outT stores for this channel issued

    // --- Epilogue: group arrival; 64th arriver transposes the strip ---
    if (tid == 0) {
        __threadfence();                               // release g_outT row
        unsigned old = atomicAdd(&g_grp[c / GRP], 1u); // monotone counter
        s_last = ((old % GRP) == (GRP - 1u)) ? 1u : 0u;
    }
    __syncthreads();
    if (!s_last) return;

    // Acquire: order our subsequent loads after the group's releases.
    __threadfence();
    __syncthreads();

    // Transpose this group's strip: rows [cBase, cBase+64) of g_outT.
    const int cBase  = (c / GRP) * GRP;
    const int tilesN = N / 64;
    float (*tile)[65] = reinterpret_cast<float(*)[65]>(sat);
    for (int tn = 0; tn < tilesN; tn++) {
        const int nBase = tn * 64;
        {   // load 64x64 tile (float4 rows of g_outT)
            const int n4 = (tid & 15) * 4;
            const int cl = tid >> 4;                   // 0..15
            #pragma unroll
            for (int k = 0; k < 4; k++) {
                int cc = cl + k * 16;
                float4 v = *reinterpret_cast<const float4*>(
                    &g_outT[(size_t)(cBase + cc) * N + nBase + n4]);
                tile[cc][n4 + 0] = v.x;
                tile[cc][n4 + 1] = v.y;
                tile[cc][n4 + 2] = v.z;
                tile[cc][n4 + 3] = v.w;
            }
        }
        __syncthreads();
        {   // store transposed (float4 rows of out)
            const int c4 = (tid & 15) * 4;
            const int nl = tid >> 4;                   // 0..15
            #pragma unroll
            for (int k = 0; k < 4; k++) {
                int nn = nl + k * 16;
                float4 v = make_float4(tile[c4 + 0][nn], tile[c4 + 1][nn],
                                       tile[c4 + 2][nn], tile[c4 + 3][nn]);
                *reinterpret_cast<float4*>(
                    &out[(size_t)(nBase + nn) * C + cBase + c4]) = v;
            }
        }
        __syncthreads();
    }
}

// ---------------------------------------------------------------------------
extern "C" void kernel_launch(void* const* d_in, const int* in_sizes, int n_in,
                              void* d_out, int out_size) {
    const float* fm  = (const float*)d_in[0];
    const float* roi = (const float*)d_in[1];
    float* out = (float*)d_out;

    int C     = in_sizes[0] / (HH * WW);
    int nrois = in_sizes[1] / 4;
    int N     = out_size / C;
    int patch_num = N / nrois;
    int p = (int)(sqrtf((float)patch_num) + 0.5f);

    int fast = (N % 64 == 0) && (C % 64 == 0) && (C <= MAX_C) &&
               (N <= MAX_PATCH);

    size_t smem = (size_t)HH * SAT_STRIDE * sizeof(float);
    cudaFuncSetAttribute(sat_pool_tr_kernel,
                         cudaFuncAttributeMaxDynamicSharedMemorySize,
                         (int)smem);
    sat_pool_tr_kernel<<<C, 256, smem>>>(fm, roi, out, C, N, nrois, p, fast);
}

// round 15
// speedup vs baseline: 2.0343x; 2.0343x over previous
#include <cuda_runtime.h>
#include <math.h>

#define HH 128
#define WW 128
#define SAT_STRIDE 132           // row stride in floats (mult of 4; data cols 4..131)
#define MAX_PATCH 8192
#define MAX_C 2048

// Scratch (no allocations allowed).
__device__ float g_outT[(size_t)MAX_C * MAX_PATCH];   // [C][N] transposed output

// ---------------------------------------------------------------------------
// Inline patch-coordinate math, bit-exact vs. the reference:
//   n = i * nrois + r ;  round == rintf (round-half-even == jnp.round)
// ---------------------------------------------------------------------------
__device__ __forceinline__ void patch_coords(
    const float4* __restrict__ roi4, int n, int nrois, int p,
    int4& q, float& inv) {
    int i = n / nrois;     // patch index within roi
    int r = n - i * nrois; // roi index

    float4 rb = roi4[r];
    float xmin = rb.x, ymin = rb.y, xmax = rb.z, ymax = rb.w;

    float ix = (float)(i % p);
    float iy = (float)(i / p);
    float pf = (float)p;

    float wstep = __fdiv_rn(__fadd_rn(xmax, -xmin), pf);
    float hstep = __fdiv_rn(__fadd_rn(ymax, -ymin), pf);

    float ax = __fadd_rn(xmin, __fmul_rn(ix, wstep));
    float ay = __fadd_rn(ymin, __fmul_rn(iy, hstep));

    int x0 = (int)rintf(ax);
    int y0 = (int)rintf(ay);
    int x1 = (int)rintf(__fadd_rn(ax, wstep));
    int y1 = (int)rintf(__fadd_rn(ay, hstep));

    // Reference divides by the RAW (unclamped) count.
    float cnt = (float)((y1 - y0) * (x1 - x0));
    inv = 1.0f / fmaxf(cnt, 1.0f);

    // Clamp only for safe SAT indexing.
    x0 = min(max(x0, 0), WW);  x1 = min(max(x1, 0), WW);
    y0 = min(max(y0, 0), HH);  y1 = min(max(y1, 0), HH);
    q = make_int4(x0, y0, x1, y1);
}

// ---------------------------------------------------------------------------
// One CTA (512 thr, 2 CTAs/SM -> 32 warps/SM) per channel.
//   Phase 1: fused load + row scan. Warp w owns rows [8w, 8w+8), two
//            batches of 4 rows (4 LDG.128 in flight, reg-capped at 63).
//   Phase 2: column scan, 2-way split (threads 0..255; conflict-free).
//   Phase 3: gather 2 patches/thread, coalesced float2 store to g_outT.
// ---------------------------------------------------------------------------
__global__ void __launch_bounds__(512, 2) sat_pool_kernel(
    const float* __restrict__ fm, const float* __restrict__ roi,
    int C, int N, int nrois, int p) {
    extern __shared__ float sat[];   // HH * SAT_STRIDE floats = 67584 B

    const int c    = blockIdx.x;
    const int tid  = threadIdx.x;
    const int warp = tid >> 5;       // 0..15
    const int lane = tid & 31;

    // --- Phase 1: fused load + row prefix scan (16 warps, 8 rows each) ---
    const float4* src =
        reinterpret_cast<const float4*>(fm + (size_t)c * HH * WW);
    #pragma unroll
    for (int half = 0; half < 2; half++) {
        const int rbase = warp * 8 + half * 4;
        float4 v[4];
        #pragma unroll
        for (int k = 0; k < 4; k++)               // 4 LDGs in flight
            v[k] = src[(rbase + k) * (WW / 4) + lane];
        #pragma unroll
        for (int k = 0; k < 4; k++) {             // independent scan chains
            float4 t = v[k];
            t.y += t.x; t.z += t.y; t.w += t.z;   // intra-quad scan
            float s = t.w;
            #pragma unroll
            for (int d = 1; d < 32; d <<= 1) {    // warp scan of quad sums
                float u = __shfl_up_sync(0xffffffffu, s, d);
                if (lane >= d) s += u;
            }
            float excl = s - t.w;
            t.x += excl; t.y += excl; t.z += excl; t.w += excl;
            *reinterpret_cast<float4*>(
                &sat[(rbase + k) * SAT_STRIDE + 4 + lane * 4]) = t;
        }
    }
    if (tid < HH) sat[tid * SAT_STRIDE + 3] = 0.0f;   // x = -1 boundary col
    __syncthreads();

    // --- Phase 2: column scan, 2-way split (threads 0..255) ---
    if (tid < 256) {
        int col  = tid & 127;            // 0..127
        int half = tid >> 7;             // 0: rows 0..63, 1: rows 64..127
        float* ptr = &sat[(half * 64) * SAT_STRIDE + 4 + col];
        float acc = 0.0f;
        #pragma unroll 8
        for (int y = 0; y < 64; y++) {
            acc += ptr[y * SAT_STRIDE];
            ptr[y * SAT_STRIDE] = acc;
        }
    }
    __syncthreads();

    // --- Phase 3: gather, 2 patches/thread, coalesced float2 store ---
    const float4* roi4 = reinterpret_cast<const float4*>(roi);
    const float* r63 = &sat[63 * SAT_STRIDE + 3];
    float* orow = &g_outT[(size_t)c * N];
    if ((N & 1) == 0) {
        for (int n2 = tid * 2; n2 < N; n2 += 1024) {
            float res[2];
            #pragma unroll
            for (int k = 0; k < 2; k++) {
                int4 q; float inv;
                patch_coords(roi4, n2 + k, nrois, p, q, inv);
                int yb = max(q.w, 1) - 1;
                int ya = max(q.y, 1) - 1;
                float mbot  = (q.y > 0) ? 1.0f : 0.0f;
                float vmask = (q.z > q.x && q.w > q.y) ? 1.0f : 0.0f;
                float d63 = r63[q.z] - r63[q.x];
                const float* rb = &sat[yb * SAT_STRIDE + 3];
                const float* ra = &sat[ya * SAT_STRIDE + 3];
                float sb = (rb[q.z] - rb[q.x]) + ((yb >= 64) ? d63 : 0.0f);
                float sa = (ra[q.z] - ra[q.x]) + ((ya >= 64) ? d63 : 0.0f);
                res[k] = (sb - mbot * sa) * vmask * inv;
            }
            *reinterpret_cast<float2*>(&orow[n2]) = make_float2(res[0], res[1]);
        }
    } else {
        for (int n = tid; n < N; n += 512) {
            int4 q; float inv;
            patch_coords(roi4, n, nrois, p, q, inv);
            int yb = max(q.w, 1) - 1;
            int ya = max(q.y, 1) - 1;
            float mbot  = (q.y > 0) ? 1.0f : 0.0f;
            float vmask = (q.z > q.x && q.w > q.y) ? 1.0f : 0.0f;
            float d63 = r63[q.z] - r63[q.x];
            const float* rb = &sat[yb * SAT_STRIDE + 3];
            const float* ra = &sat[ya * SAT_STRIDE + 3];
            float sb = (rb[q.z] - rb[q.x]) + ((yb >= 64) ? d63 : 0.0f);
            float sa = (ra[q.z] - ra[q.x]) + ((ya >= 64) ? d63 : 0.0f);
            orow[n] = (sb - mbot * sa) * vmask * inv;
        }
    }
}

// ---------------------------------------------------------------------------
// Tiled transpose g_outT[C][N] -> out[N][C], 64x64 tiles, float4 on both
// global sides (4x LDG.128 + 4x STG.128 per thread = 128 B/thread).
// ---------------------------------------------------------------------------
__global__ void __launch_bounds__(256) transpose64_kernel(
    float* __restrict__ out, int C, int N) {
    __shared__ float tile[64][65];
    const int nBase = blockIdx.x * 64;
    const int cBase = blockIdx.y * 64;
    const int tid = threadIdx.x;

    {
        const int n4 = (tid & 15) * 4;
        const int cl = tid >> 4;            // 0..15
        #pragma unroll
        for (int k = 0; k < 4; k++) {
            int cc = cl + k * 16;
            float4 v = *reinterpret_cast<const float4*>(
                &g_outT[(size_t)(cBase + cc) * N + nBase + n4]);
            tile[cc][n4 + 0] = v.x;
            tile[cc][n4 + 1] = v.y;
            tile[cc][n4 + 2] = v.z;
            tile[cc][n4 + 3] = v.w;
        }
    }
    __syncthreads();
    {
        const int c4 = (tid & 15) * 4;
        const int nl = tid >> 4;            // 0..15
        #pragma unroll
        for (int k = 0; k < 4; k++) {
            int nn = nl + k * 16;
            float4 v = make_float4(tile[c4 + 0][nn], tile[c4 + 1][nn],
                                   tile[c4 + 2][nn], tile[c4 + 3][nn]);
            *reinterpret_cast<float4*>(
                &out[(size_t)(nBase + nn) * C + cBase + c4]) = v;
        }
    }
}

// Fallback for non-multiple-of-64 shapes (not hit for this problem).
__global__ void __launch_bounds__(256) transpose32_kernel(
    float* __restrict__ out, int C, int N) {
    __shared__ float tile[32][33];
    int nBase = blockIdx.x * 32;
    int cBase = blockIdx.y * 32;
    int tx = threadIdx.x & 31;
    int ty = threadIdx.x >> 5;   // 0..7
    #pragma unroll
    for (int k = 0; k < 32; k += 8) {
        int cc = cBase + ty + k, nn = nBase + tx;
        if (cc < C && nn < N)
            tile[ty + k][tx] = g_outT[(size_t)cc * N + nn];
    }
    __syncthreads();
    #pragma unroll
    for (int k = 0; k < 32; k += 8) {
        int nn = nBase + ty + k, cc = cBase + tx;
        if (nn < N && cc < C)
            out[(size_t)nn * C + cc] = tile[tx][ty + k];
    }
}

// ---------------------------------------------------------------------------
extern "C" void kernel_launch(void* const* d_in, const int* in_sizes, int n_in,
                              void* d_out, int out_size) {
    const float* fm  = (const float*)d_in[0];
    const float* roi = (const float*)d_in[1];
    float* out = (float*)d_out;

    int C     = in_sizes[0] / (HH * WW);
    int nrois = in_sizes[1] / 4;
    int N     = out_size / C;
    int patch_num = N / nrois;
    int p = (int)(sqrtf((float)patch_num) + 0.5f);

    size_t smem = (size_t)HH * SAT_STRIDE * sizeof(float);
    cudaFuncSetAttribute(sat_pool_kernel,
                         cudaFuncAttributeMaxDynamicSharedMemorySize,
                         (int)smem);
    sat_pool_kernel<<<C, 512, smem>>>(fm, roi, C, N, nrois, p);

    if ((N % 64 == 0) && (C % 64 == 0)) {
        dim3 tgrid(N / 64, C / 64);
        transpose64_kernel<<<tgrid, 256>>>(out, C, N);
    } else {
        dim3 tgrid((N + 31) / 32, (C + 31) / 32);
        transpose32_kernel<<<tgrid, 256>>>(out, C, N);
    }
}